// round 2
// baseline (speedup 1.0000x reference)
#include <cuda_runtime.h>

// Problem constants (fixed by setup_inputs)
#define B_     8
#define N_     3072
#define D_     1024
#define D4_    256          // D/4 (float4)
#define STEPS  1024         // N/POOL
#define POOL_  3
#define NC_    16           // chunks over steps
#define CHUNK_ 64           // steps per chunk
#define EPS_   0.006f

// Scratch (no allocations allowed): window-level prefix sums + chunk scan temps
__device__ float g_P [(size_t)B_ * (STEPS + 1) * D_];   // ~33.6 MB
__device__ float g_S [B_ * NC_ * D_];                   // chunk sums
__device__ float g_SP[B_ * NC_ * D_];                   // exclusive scan of chunk sums
__device__ int   g_is32;                                // 1 if graph is int32, 0 if int64

__device__ __forceinline__ float4 f4add(float4 a, float4 b) {
    return make_float4(a.x + b.x, a.y + b.y, a.z + b.z, a.w + b.w);
}
__device__ __forceinline__ float4 f4sub(float4 a, float4 b) {
    return make_float4(a.x - b.x, a.y - b.y, a.z - b.z, a.w - b.w);
}

// ---------------------------------------------------------------------------
// 0) dtype detection for graph: int64 little-endian => odd 32-bit words of the
//    first 8192 entries are all zero (values in [0, N)). int32 => odd words
//    are 'e' endpoints, essentially never all zero.
// ---------------------------------------------------------------------------
__global__ void k_detect(const unsigned int* __restrict__ g) {
    __shared__ unsigned int sh[256];
    unsigned int v = 0;
    for (int i = threadIdx.x; i < 8192; i += 256) v |= g[2 * i + 1];
    sh[threadIdx.x] = v;
    __syncthreads();
    for (int o = 128; o > 0; o >>= 1) {
        if (threadIdx.x < o) sh[threadIdx.x] |= sh[threadIdx.x + o];
        __syncthreads();
    }
    if (threadIdx.x == 0) g_is32 = (sh[0] != 0u) ? 1 : 0;
}

// ---------------------------------------------------------------------------
// 1) Window means -> output odd rows. One block per (b, t); 256 thr x float4.
// ---------------------------------------------------------------------------
__global__ void __launch_bounds__(256) k_win(const float4* __restrict__ x,
                                             float4* __restrict__ out) {
    int bt = blockIdx.x;
    int b = bt >> 10, t = bt & 1023;
    int i = threadIdx.x;
    const float4* xr = x + (size_t)(b * N_ + POOL_ * t) * D4_;
    float4 a = xr[i];
    float4 c = xr[i + D4_];
    float4 d = xr[i + 2 * D4_];
    const float inv3 = 1.0f / 3.0f;
    float4 w = make_float4((a.x + c.x + d.x) * inv3,
                           (a.y + c.y + d.y) * inv3,
                           (a.z + c.z + d.z) * inv3,
                           (a.w + c.w + d.w) * inv3);
    out[(size_t)(b * 2 * STEPS + 2 * t + 1) * D4_ + i] = w;
}

// ---------------------------------------------------------------------------
// 2) Chunk sums: S[b,c,d] = 3 * sum_{t in chunk c} win[b,t,d]
//    grid = B*NC*4, 256 threads (d-tile of 256)
// ---------------------------------------------------------------------------
__global__ void __launch_bounds__(256) k_chunksum(const float* __restrict__ out) {
    int blk = blockIdx.x;
    int dq = blk & 3, c = (blk >> 2) & 15, b = blk >> 6;
    int d = dq * 256 + threadIdx.x;
    const float* w = out + ((size_t)b * 2 * STEPS + 1) * D_ + d;  // win rows: +2t*D_
    int t0 = c * CHUNK_;
    float s0 = 0.f, s1 = 0.f, s2 = 0.f, s3 = 0.f;
#pragma unroll
    for (int i = 0; i < CHUNK_; i += 4) {
        s0 += w[(size_t)(2 * (t0 + i    )) * D_];
        s1 += w[(size_t)(2 * (t0 + i + 1)) * D_];
        s2 += w[(size_t)(2 * (t0 + i + 2)) * D_];
        s3 += w[(size_t)(2 * (t0 + i + 3)) * D_];
    }
    g_S[(size_t)(b * NC_ + c) * D_ + d] = 3.0f * ((s0 + s1) + (s2 + s3));
}

// ---------------------------------------------------------------------------
// 3) Tiny exclusive scan of the 16 chunk sums per (b,d). grid=32x256.
// ---------------------------------------------------------------------------
__global__ void __launch_bounds__(256) k_scan16() {
    int idx = blockIdx.x * 256 + threadIdx.x;   // 0..8191
    int b = idx >> 10, d = idx & 1023;
    float run = 0.f;
#pragma unroll
    for (int c = 0; c < NC_; c++) {
        size_t o = (size_t)(b * NC_ + c) * D_ + d;
        g_SP[o] = run;
        run += g_S[o];
    }
}

// ---------------------------------------------------------------------------
// 4) Window-level inclusive prefix: P[b,q,d] = sum_{t<q} (3*win[b,t,d])
//    Each block finishes one chunk using its exclusive offset.
// ---------------------------------------------------------------------------
__global__ void __launch_bounds__(256) k_prefix(const float* __restrict__ out) {
    int blk = blockIdx.x;
    int dq = blk & 3, c = (blk >> 2) & 15, b = blk >> 6;
    int d = dq * 256 + threadIdx.x;
    float run = g_SP[(size_t)(b * NC_ + c) * D_ + d];
    const float* w = out + ((size_t)b * 2 * STEPS + 1) * D_ + d;
    float* P = g_P + (size_t)b * (STEPS + 1) * D_ + d;
    int q0 = c * CHUNK_;
    P[(size_t)q0 * D_] = run;
#pragma unroll 4
    for (int i = 0; i < CHUNK_; i++) {
        run += 3.0f * w[(size_t)(2 * (q0 + i)) * D_];
        P[(size_t)(q0 + i + 1) * D_] = run;
    }
}

// ---------------------------------------------------------------------------
// 5) Gather: seg_mean[b,t,:] = (pref(e+1)-pref(s))/(e-s+1) + EPS
//    pref(k) = P[k/3] + sum of (k%3) residual x rows. One block per (b,t).
// ---------------------------------------------------------------------------
__global__ void __launch_bounds__(256) k_gather(const float4* __restrict__ x,
                                                const void* __restrict__ graph,
                                                float4* __restrict__ out) {
    int bt = blockIdx.x;
    int b = bt >> 10, t = bt & 1023;
    int s, e;
    if (g_is32) {
        const int* g = (const int*)graph;
        s = g[2 * bt]; e = g[2 * bt + 1];
    } else {
        const long long* g = (const long long*)graph;
        s = (int)g[2 * bt]; e = (int)g[2 * bt + 1];
    }
    int ke = e + 1, ks = s;
    int qe = ke / 3, re = ke - 3 * qe;
    int qs = ks / 3, rs = ks - 3 * qs;
    int i = threadIdx.x;

    const float4* P4 = (const float4*)g_P + (size_t)b * (STEPS + 1) * D4_;
    const float4* x4 = x + (size_t)b * N_ * D4_;

    float4 acc = f4sub(P4[(size_t)qe * D4_ + i], P4[(size_t)qs * D4_ + i]);
#pragma unroll
    for (int r = 0; r < 2; r++)
        if (r < re) acc = f4add(acc, x4[(size_t)(3 * qe + r) * D4_ + i]);
#pragma unroll
    for (int r = 0; r < 2; r++)
        if (r < rs) acc = f4sub(acc, x4[(size_t)(3 * qs + r) * D4_ + i]);

    float inv = 1.0f / (float)(ke - ks);
    float4 o = make_float4(acc.x * inv + EPS_, acc.y * inv + EPS_,
                           acc.z * inv + EPS_, acc.w * inv + EPS_);
    out[(size_t)(b * 2 * STEPS + 2 * t) * D4_ + i] = o;
}

// ---------------------------------------------------------------------------
extern "C" void kernel_launch(void* const* d_in, const int* in_sizes, int n_in,
                              void* d_out, int out_size) {
    const float* x     = (const float*)d_in[0];
    const void*  graph = d_in[1];
    float*       out   = (float*)d_out;

    k_detect  <<<1, 256>>>((const unsigned int*)graph);
    k_win     <<<B_ * STEPS, 256>>>((const float4*)x, (float4*)out);
    k_chunksum<<<B_ * NC_ * 4, 256>>>(out);
    k_scan16  <<<32, 256>>>();
    k_prefix  <<<B_ * NC_ * 4, 256>>>(out);
    k_gather  <<<B_ * STEPS, 256>>>((const float4*)x, graph, (float4*)out);
}

// round 3
// speedup vs baseline: 1.2429x; 1.2429x over previous
#include <cuda_runtime.h>

// Problem constants (fixed by setup_inputs)
#define B_     8
#define N_     3072
#define D_     1024
#define D4_    256          // D/4 (float4)
#define STEPS  1024         // N/POOL
#define POOL_  3
#define NCH    64           // chunks per batch
#define CWIN   16           // windows per chunk
#define EPS_   0.006f

// Scratch (__device__ globals; no allocations allowed)
__device__ float g_L [(size_t)B_ * (STEPS + 1) * D_];  // chunk-local exclusive prefix (~33.6 MB)
__device__ float g_S [(size_t)B_ * NCH * D_];          // chunk totals (2 MB)
__device__ float g_SP[(size_t)B_ * (NCH + 1) * D_];    // exclusive scan of chunk totals (2.1 MB)
__device__ int   g_is32;                               // 1 if graph is int32, 0 if int64

__device__ __forceinline__ float4 f4add(float4 a, float4 b) {
    return make_float4(a.x + b.x, a.y + b.y, a.z + b.z, a.w + b.w);
}
__device__ __forceinline__ float4 f4sub(float4 a, float4 b) {
    return make_float4(a.x - b.x, a.y - b.y, a.z - b.z, a.w - b.w);
}

// ---------------------------------------------------------------------------
// 0) graph dtype detection: int64 LE => odd 32-bit words all zero (values < N).
// ---------------------------------------------------------------------------
__global__ void k_detect(const unsigned int* __restrict__ g) {
    __shared__ unsigned int sh[256];
    unsigned int v = 0;
    for (int i = threadIdx.x; i < 8192; i += 256) v |= g[2 * i + 1];
    sh[threadIdx.x] = v;
    __syncthreads();
    for (int o = 128; o > 0; o >>= 1) {
        if (threadIdx.x < o) sh[threadIdx.x] |= sh[threadIdx.x + o];
        __syncthreads();
    }
    if (threadIdx.x == 0) g_is32 = (sh[0] != 0u) ? 1 : 0;
}

// ---------------------------------------------------------------------------
// 1) Fused pass over x: per (b, chunk) block of 16 windows x full D (float4).
//    Writes: window means -> out odd rows, chunk-local exclusive prefix -> L,
//    chunk total -> S. Single read of x.
// ---------------------------------------------------------------------------
__global__ void __launch_bounds__(256) k_fused(const float4* __restrict__ x,
                                               float4* __restrict__ out) {
    int blk = blockIdx.x;               // B*NCH = 512 blocks
    int b = blk >> 6, c = blk & 63;
    int q0 = c * CWIN;
    int i = threadIdx.x;

    const float4* xr = x + ((size_t)(b * N_ + POOL_ * q0)) * D4_ + i;
    float4* L4 = (float4*)g_L + ((size_t)b * (STEPS + 1) + q0) * D4_ + i;
    float4* o4 = out + ((size_t)(b * 2 * STEPS) + 2 * q0 + 1) * D4_ + i;

    const float inv3 = 1.0f / 3.0f;
    float4 run = make_float4(0.f, 0.f, 0.f, 0.f);
#pragma unroll
    for (int w = 0; w < CWIN; w++) {
        float4 a = xr[(size_t)(3 * w) * D4_];
        float4 bb = xr[(size_t)(3 * w + 1) * D4_];
        float4 cc = xr[(size_t)(3 * w + 2) * D4_];
        L4[(size_t)w * D4_] = run;                       // exclusive local prefix
        float4 sum = f4add(f4add(a, bb), cc);            // raw row-sum (= 3*mean)
        o4[(size_t)(2 * w) * D4_] = make_float4(sum.x * inv3, sum.y * inv3,
                                                sum.z * inv3, sum.w * inv3);
        run = f4add(run, sum);
    }
    ((float4*)g_S)[((size_t)b * NCH + c) * D4_ + i] = run;
}

// ---------------------------------------------------------------------------
// 2) Scan chunk totals: batch ALL 64 loads first (MLP=64), then scan in regs.
//    Also zero-fills L[b][STEPS][*] so pref(q=1024) = SP[64] works.
// ---------------------------------------------------------------------------
__global__ void __launch_bounds__(256) k_scan64() {
    int idx = blockIdx.x * 256 + threadIdx.x;   // 0..8191
    int b = idx >> 10, d = idx & 1023;
    const float* S = g_S + (size_t)b * NCH * D_ + d;
    float v[NCH];
#pragma unroll
    for (int c = 0; c < NCH; c++) v[c] = S[(size_t)c * D_];
    float* SPp = g_SP + (size_t)b * (NCH + 1) * D_ + d;
    float run = 0.f;
#pragma unroll
    for (int c = 0; c < NCH; c++) { SPp[(size_t)c * D_] = run; run += v[c]; }
    SPp[(size_t)NCH * D_] = run;
    g_L[((size_t)b * (STEPS + 1) + STEPS) * D_ + d] = 0.f;
}

// ---------------------------------------------------------------------------
// 3) Gather: pref(q) = SP[q>>4] + L[q]; seg = (pref(qe)+res_e - pref(qs)-res_s)
//            / (e-s+1) + EPS. One block per (b,t).
// ---------------------------------------------------------------------------
__global__ void __launch_bounds__(256) k_gather(const float4* __restrict__ x,
                                                const void* __restrict__ graph,
                                                float4* __restrict__ out) {
    int bt = blockIdx.x;
    int b = bt >> 10, t = bt & 1023;
    int s, e;
    if (g_is32) {
        const int* g = (const int*)graph;
        s = g[2 * bt]; e = g[2 * bt + 1];
    } else {
        const long long* g = (const long long*)graph;
        s = (int)g[2 * bt]; e = (int)g[2 * bt + 1];
    }
    int ke = e + 1, ks = s;
    int qe = ke / 3, re = ke - 3 * qe;
    int qs = ks / 3, rs = ks - 3 * qs;
    int i = threadIdx.x;

    const float4* L4  = (const float4*)g_L  + (size_t)b * (STEPS + 1) * D4_;
    const float4* SP4 = (const float4*)g_SP + (size_t)b * (NCH + 1) * D4_;
    const float4* x4  = x + (size_t)b * N_ * D4_;

    float4 pe = f4add(L4[(size_t)qe * D4_ + i], SP4[(size_t)(qe >> 4) * D4_ + i]);
    float4 ps = f4add(L4[(size_t)qs * D4_ + i], SP4[(size_t)(qs >> 4) * D4_ + i]);
    float4 acc = f4sub(pe, ps);
#pragma unroll
    for (int r = 0; r < 2; r++)
        if (r < re) acc = f4add(acc, x4[(size_t)(3 * qe + r) * D4_ + i]);
#pragma unroll
    for (int r = 0; r < 2; r++)
        if (r < rs) acc = f4sub(acc, x4[(size_t)(3 * qs + r) * D4_ + i]);

    float inv = 1.0f / (float)(ke - ks);
    float4 o = make_float4(acc.x * inv + EPS_, acc.y * inv + EPS_,
                           acc.z * inv + EPS_, acc.w * inv + EPS_);
    out[(size_t)(b * 2 * STEPS + 2 * t) * D4_ + i] = o;
}

// ---------------------------------------------------------------------------
extern "C" void kernel_launch(void* const* d_in, const int* in_sizes, int n_in,
                              void* d_out, int out_size) {
    const float* x     = (const float*)d_in[0];
    const void*  graph = d_in[1];
    float*       out   = (float*)d_out;

    k_detect<<<1, 256>>>((const unsigned int*)graph);
    k_fused <<<B_ * NCH, 256>>>((const float4*)x, (float4*)out);
    k_scan64<<<32, 256>>>();
    k_gather<<<B_ * STEPS, 256>>>((const float4*)x, graph, (float4*)out);
}

// round 4
// speedup vs baseline: 1.3385x; 1.0769x over previous
#include <cuda_runtime.h>

// Problem constants (fixed by setup_inputs)
#define B_     8
#define N_     3072
#define D_     1024
#define D4_    256          // D/4 (float4)
#define STEPS  1024         // N/POOL
#define POOL_  3
#define NCH    64           // chunks per batch
#define CWIN   16           // windows per chunk
#define EPS_   0.006f

// Scratch (__device__ globals; no allocations allowed)
__device__ float g_L [(size_t)B_ * (STEPS + 1) * D_];  // chunk-local exclusive window prefix
__device__ float g_S [(size_t)B_ * NCH * D_];          // chunk totals
__device__ float g_SP[(size_t)B_ * (NCH + 1) * D_];    // exclusive scan of chunk totals
__device__ int   g_is32;                               // 1 if graph is int32
__device__ int4  g_idx[B_ * STEPS];                    // packed (qe,resE,qs,resS)
__device__ float g_inv[B_ * STEPS];                    // 1/len per segment

__device__ __forceinline__ float4 f4add(float4 a, float4 b) {
    return make_float4(a.x + b.x, a.y + b.y, a.z + b.z, a.w + b.w);
}
__device__ __forceinline__ float4 f4sub(float4 a, float4 b) {
    return make_float4(a.x - b.x, a.y - b.y, a.z - b.z, a.w - b.w);
}
__device__ __forceinline__ float4 ldcs4(const float4* p) {
    return __ldcs(p);   // evict-first streaming load
}
__device__ __forceinline__ void stcs4(float4* p, float4 v) {
    __stcs(p, v);       // evict-first streaming store
}

// ---------------------------------------------------------------------------
// 0) graph dtype detection: int64 LE => odd 32-bit words all zero (values < N).
// ---------------------------------------------------------------------------
__global__ void k_detect(const unsigned int* __restrict__ g) {
    __shared__ unsigned int sh[256];
    unsigned int v = 0;
    for (int i = threadIdx.x; i < 8192; i += 256) v |= g[2 * i + 1];
    sh[threadIdx.x] = v;
    __syncthreads();
    for (int o = 128; o > 0; o >>= 1) {
        if (threadIdx.x < o) sh[threadIdx.x] |= sh[threadIdx.x + o];
        __syncthreads();
    }
    if (threadIdx.x == 0) g_is32 = (sh[0] != 0u) ? 1 : 0;
}

// ---------------------------------------------------------------------------
// 0b) Precompute per-segment indices with the ceiling trick.
//     Boundary k: k=3q+r.  r==0 -> (q, none)
//                          r==1 -> (q, row 3q)        [+ for end, - for start]
//                          r==2 -> (q+1, row 3q+2)    [- for end, + for start]
//     Residual encoding: 0 = none, +(row+1) = add x row, -(row+1) = subtract.
// ---------------------------------------------------------------------------
__global__ void __launch_bounds__(256) k_prep(const void* __restrict__ graph) {
    int bt = blockIdx.x * 256 + threadIdx.x;     // 0..8191
    int s, e;
    if (g_is32) {
        const int* g = (const int*)graph;
        s = g[2 * bt]; e = g[2 * bt + 1];
    } else {
        const long long* g = (const long long*)graph;
        s = (int)g[2 * bt]; e = (int)g[2 * bt + 1];
    }
    int ke = e + 1, ks = s;
    // end boundary (added)
    int qe = ke / 3, re = ke - 3 * qe, resE = 0;
    if (re == 1) resE = (3 * qe) + 1;            // + x[3q]
    else if (re == 2) { qe += 1; resE = -((3 * (qe - 1) + 2) + 1); }  // - x[3q+2]
    // start boundary (subtracted) -> signs flipped
    int qs = ks / 3, rs = ks - 3 * qs, resS = 0;
    if (rs == 1) resS = -((3 * qs) + 1);         // - x[3q]
    else if (rs == 2) { qs += 1; resS = (3 * (qs - 1) + 2) + 1; }     // + x[3q+2]
    g_idx[bt] = make_int4(qe, resE, qs, resS);
    g_inv[bt] = 1.0f / (float)(ke - ks);
}

// ---------------------------------------------------------------------------
// 1) Fused pass over x (streamed): window means -> out odd rows (streamed),
//    chunk-local exclusive prefix -> L (L2-resident), chunk total -> S.
// ---------------------------------------------------------------------------
__global__ void __launch_bounds__(256) k_fused(const float4* __restrict__ x,
                                               float4* __restrict__ out) {
    int blk = blockIdx.x;               // B*NCH = 512 blocks
    int b = blk >> 6, c = blk & 63;
    int q0 = c * CWIN;
    int i = threadIdx.x;

    const float4* xr = x + ((size_t)(b * N_ + POOL_ * q0)) * D4_ + i;
    float4* L4 = (float4*)g_L + ((size_t)b * (STEPS + 1) + q0) * D4_ + i;
    float4* o4 = out + ((size_t)(b * 2 * STEPS) + 2 * q0 + 1) * D4_ + i;

    const float inv3 = 1.0f / 3.0f;
    float4 run = make_float4(0.f, 0.f, 0.f, 0.f);
#pragma unroll
    for (int w = 0; w < CWIN; w++) {
        float4 a  = ldcs4(&xr[(size_t)(3 * w)     * D4_]);
        float4 bb = ldcs4(&xr[(size_t)(3 * w + 1) * D4_]);
        float4 cc = ldcs4(&xr[(size_t)(3 * w + 2) * D4_]);
        L4[(size_t)w * D4_] = run;                       // keep in L2
        float4 sum = f4add(f4add(a, bb), cc);            // raw row-sum
        stcs4(&o4[(size_t)(2 * w) * D4_],
              make_float4(sum.x * inv3, sum.y * inv3, sum.z * inv3, sum.w * inv3));
        run = f4add(run, sum);
    }
    ((float4*)g_S)[((size_t)b * NCH + c) * D4_ + i] = run;
}

// ---------------------------------------------------------------------------
// 2) Scan chunk totals (batch loads first for MLP=64); zero-fill L[b][STEPS].
// ---------------------------------------------------------------------------
__global__ void __launch_bounds__(256) k_scan64() {
    int idx = blockIdx.x * 256 + threadIdx.x;   // 0..8191
    int b = idx >> 10, d = idx & 1023;
    const float* S = g_S + (size_t)b * NCH * D_ + d;
    float v[NCH];
#pragma unroll
    for (int c = 0; c < NCH; c++) v[c] = S[(size_t)c * D_];
    float* SPp = g_SP + (size_t)b * (NCH + 1) * D_ + d;
    float run = 0.f;
#pragma unroll
    for (int c = 0; c < NCH; c++) { SPp[(size_t)c * D_] = run; run += v[c]; }
    SPp[(size_t)NCH * D_] = run;
    g_L[((size_t)b * (STEPS + 1) + STEPS) * D_ + d] = 0.f;
}

// ---------------------------------------------------------------------------
// 3) Gather: acc = (L[qe]+SP[qe>>4]) - (L[qs]+SP[qs>>4]) +/- residual x rows.
//    L/SP reads are L2 hits; residual x reads streamed; out writes streamed.
// ---------------------------------------------------------------------------
__global__ void __launch_bounds__(256) k_gather(const float4* __restrict__ x,
                                                float4* __restrict__ out) {
    int bt = blockIdx.x;
    int b = bt >> 10;
    int4 w = g_idx[bt];
    float invlen = g_inv[bt];
    int i = threadIdx.x;

    const float4* L4  = (const float4*)g_L  + (size_t)b * (STEPS + 1) * D4_;
    const float4* SP4 = (const float4*)g_SP + (size_t)b * (NCH + 1) * D4_;
    const float4* x4  = x + (size_t)b * N_ * D4_;

    float4 pe = f4add(L4[(size_t)w.x * D4_ + i], SP4[(size_t)(w.x >> 4) * D4_ + i]);
    float4 ps = f4add(L4[(size_t)w.z * D4_ + i], SP4[(size_t)(w.z >> 4) * D4_ + i]);
    float4 acc = f4sub(pe, ps);

    if (w.y != 0) {
        int row = (w.y > 0 ? w.y : -w.y) - 1;
        float sgn = (w.y > 0) ? 1.f : -1.f;
        float4 v = ldcs4(&x4[(size_t)row * D4_ + i]);
        acc = make_float4(fmaf(sgn, v.x, acc.x), fmaf(sgn, v.y, acc.y),
                          fmaf(sgn, v.z, acc.z), fmaf(sgn, v.w, acc.w));
    }
    if (w.w != 0) {
        int row = (w.w > 0 ? w.w : -w.w) - 1;
        float sgn = (w.w > 0) ? 1.f : -1.f;
        float4 v = ldcs4(&x4[(size_t)row * D4_ + i]);
        acc = make_float4(fmaf(sgn, v.x, acc.x), fmaf(sgn, v.y, acc.y),
                          fmaf(sgn, v.z, acc.z), fmaf(sgn, v.w, acc.w));
    }

    float4 o = make_float4(acc.x * invlen + EPS_, acc.y * invlen + EPS_,
                           acc.z * invlen + EPS_, acc.w * invlen + EPS_);
    stcs4(&out[(size_t)(2 * bt) * D4_ + i], o);
}

// ---------------------------------------------------------------------------
extern "C" void kernel_launch(void* const* d_in, const int* in_sizes, int n_in,
                              void* d_out, int out_size) {
    const float* x     = (const float*)d_in[0];
    const void*  graph = d_in[1];
    float*       out   = (float*)d_out;

    k_detect<<<1, 256>>>((const unsigned int*)graph);
    k_prep  <<<32, 256>>>(graph);
    k_fused <<<B_ * NCH, 256>>>((const float4*)x, (float4*)out);
    k_scan64<<<32, 256>>>();
    k_gather<<<B_ * STEPS, 256>>>((const float4*)x, (float4*)out);
}

// round 6
// speedup vs baseline: 1.3454x; 1.0052x over previous
#include <cuda_runtime.h>

// Problem constants (fixed by setup_inputs)
#define B_     8
#define N_     3072
#define D_     1024
#define D4_    256          // D/4 (float4)
#define STEPS  1024         // N/POOL
#define POOL_  3
#define NCH    64           // chunks per batch
#define CWIN   16           // windows per chunk
#define EPS_   0.006f

// Scratch (__device__ globals; no allocations allowed)
__device__ float g_L [(size_t)B_ * (STEPS + 1) * D_];  // chunk-local exclusive window prefix
__device__ float g_S [(size_t)B_ * NCH * D_];          // chunk totals
__device__ float g_SP[(size_t)B_ * (NCH + 1) * D_];    // exclusive scan of chunk totals
__device__ int   g_is32;                               // 1 if graph is int32
__device__ int4  g_idx[B_ * STEPS];                    // packed (qe,resE,qs,resS)
__device__ float g_inv[B_ * STEPS];                    // 1/len per segment

__device__ __forceinline__ float4 f4add(float4 a, float4 b) {
    return make_float4(a.x + b.x, a.y + b.y, a.z + b.z, a.w + b.w);
}
__device__ __forceinline__ float4 f4sub(float4 a, float4 b) {
    return make_float4(a.x - b.x, a.y - b.y, a.z - b.z, a.w - b.w);
}
__device__ __forceinline__ float4 ldcs4(const float4* p) { return __ldcs(p); }
__device__ __forceinline__ void stcs4(float4* p, float4 v) { __stcs(p, v); }

// ---------------------------------------------------------------------------
// 0) graph dtype detection (sampled): int64 LE => odd 32-bit words all zero.
// ---------------------------------------------------------------------------
__global__ void k_detect(const unsigned int* __restrict__ g) {
    __shared__ unsigned int sh[256];
    unsigned int v = 0;
    for (int i = threadIdx.x; i < 1024; i += 256) v |= g[2 * i + 1];
    sh[threadIdx.x] = v;
    __syncthreads();
    for (int o = 128; o > 0; o >>= 1) {
        if (threadIdx.x < o) sh[threadIdx.x] |= sh[threadIdx.x + o];
        __syncthreads();
    }
    if (threadIdx.x == 0) g_is32 = (sh[0] != 0u) ? 1 : 0;
}

// ---------------------------------------------------------------------------
// 0b) Precompute per-segment indices (ceiling trick).
//     Residual encoding: 0 = none, +(row+1) = add x row, -(row+1) = subtract.
// ---------------------------------------------------------------------------
__global__ void __launch_bounds__(256) k_prep(const void* __restrict__ graph) {
    int bt = blockIdx.x * 256 + threadIdx.x;     // 0..8191
    int s, e;
    if (g_is32) {
        const int* g = (const int*)graph;
        s = g[2 * bt]; e = g[2 * bt + 1];
    } else {
        const long long* g = (const long long*)graph;
        s = (int)g[2 * bt]; e = (int)g[2 * bt + 1];
    }
    int ke = e + 1, ks = s;
    int qe = ke / 3, re = ke - 3 * qe, resE = 0;
    if (re == 1) resE = (3 * qe) + 1;                                  // + x[3q]
    else if (re == 2) { qe += 1; resE = -((3 * (qe - 1) + 2) + 1); }   // - x[3q+2]
    int qs = ks / 3, rs = ks - 3 * qs, resS = 0;
    if (rs == 1) resS = -((3 * qs) + 1);                               // - x[3q]
    else if (rs == 2) { qs += 1; resS = (3 * (qs - 1) + 2) + 1; }      // + x[3q+2]
    g_idx[bt] = make_int4(qe, resE, qs, resS);
    g_inv[bt] = 1.0f / (float)(ke - ks);
}

// ---------------------------------------------------------------------------
// 1) Fused pass over x (streamed): window means -> out odd rows (streamed),
//    chunk-local exclusive prefix -> L (L2-resident), chunk total -> S.
// ---------------------------------------------------------------------------
__global__ void __launch_bounds__(256) k_fused(const float4* __restrict__ x,
                                               float4* __restrict__ out) {
    int blk = blockIdx.x;               // B*NCH = 512 blocks
    int b = blk >> 6, c = blk & 63;
    int q0 = c * CWIN;
    int i = threadIdx.x;

    const float4* xr = x + ((size_t)(b * N_ + POOL_ * q0)) * D4_ + i;
    float4* L4 = (float4*)g_L + ((size_t)b * (STEPS + 1) + q0) * D4_ + i;
    float4* o4 = out + ((size_t)(b * 2 * STEPS) + 2 * q0 + 1) * D4_ + i;

    const float inv3 = 1.0f / 3.0f;
    float4 run = make_float4(0.f, 0.f, 0.f, 0.f);
#pragma unroll
    for (int w = 0; w < CWIN; w++) {
        float4 a  = ldcs4(&xr[(size_t)(3 * w)     * D4_]);
        float4 bb = ldcs4(&xr[(size_t)(3 * w + 1) * D4_]);
        float4 cc = ldcs4(&xr[(size_t)(3 * w + 2) * D4_]);
        L4[(size_t)w * D4_] = run;                       // keep in L2
        float4 sum = f4add(f4add(a, bb), cc);            // raw row-sum
        stcs4(&o4[(size_t)(2 * w) * D4_],
              make_float4(sum.x * inv3, sum.y * inv3, sum.z * inv3, sum.w * inv3));
        run = f4add(run, sum);
    }
    ((float4*)g_S)[((size_t)b * NCH + c) * D4_ + i] = run;
}

// ---------------------------------------------------------------------------
// 2) Hierarchical scan of chunk totals, spill-free.
//    Grid: 256 blocks = b(8) x d-tile(32 of 32 d). Block: 32 d-lanes x 8 groups.
//    Each thread: sum 8 chunks (v[8] in regs, MLP=8) -> shared 8-way exclusive
//    scan per d-lane -> emit 8 SP entries. Also zero-fills L[b][STEPS][*] and
//    writes SP[64].
// ---------------------------------------------------------------------------
__global__ void __launch_bounds__(256) k_scan() {
    __shared__ float sh[8][32];
    int blk = blockIdx.x;               // 256 blocks
    int b = blk >> 5, dt = blk & 31;
    int dl = threadIdx.x & 31;          // d-lane within tile
    int gr = threadIdx.x >> 5;          // chunk group 0..7
    int d = dt * 32 + dl;

    const float* S = g_S + (size_t)b * NCH * D_ + d;
    float v[8];
#pragma unroll
    for (int j = 0; j < 8; j++) v[j] = S[(size_t)(gr * 8 + j) * D_];
    float gsum = ((v[0] + v[1]) + (v[2] + v[3])) + ((v[4] + v[5]) + (v[6] + v[7]));
    sh[gr][dl] = gsum;
    __syncthreads();

    float off = 0.f;
#pragma unroll
    for (int j = 0; j < 8; j++) { float t = sh[j][dl]; if (j < gr) off += t; }

    float* SPp = g_SP + (size_t)b * (NCH + 1) * D_ + d;
    float run = off;
#pragma unroll
    for (int j = 0; j < 8; j++) {
        SPp[(size_t)(gr * 8 + j) * D_] = run;
        run += v[j];
    }
    if (gr == 7) {
        SPp[(size_t)NCH * D_] = run;                              // SP[64] = total
        g_L[((size_t)b * (STEPS + 1) + STEPS) * D_ + d] = 0.f;    // L[q=STEPS] = 0
    }
}

// ---------------------------------------------------------------------------
// 3) Gather: acc = (L[qe]+SP[qe>>4]) - (L[qs]+SP[qs>>4]) +/- residual x rows.
// ---------------------------------------------------------------------------
__global__ void __launch_bounds__(256) k_gather(const float4* __restrict__ x,
                                                float4* __restrict__ out) {
    int bt = blockIdx.x;
    int b = bt >> 10;
    int4 w = g_idx[bt];
    float invlen = g_inv[bt];
    int i = threadIdx.x;

    const float4* L4  = (const float4*)g_L  + (size_t)b * (STEPS + 1) * D4_;
    const float4* SP4 = (const float4*)g_SP + (size_t)b * (NCH + 1) * D4_;
    const float4* x4  = x + (size_t)b * N_ * D4_;

    float4 pe = f4add(L4[(size_t)w.x * D4_ + i], SP4[(size_t)(w.x >> 4) * D4_ + i]);
    float4 ps = f4add(L4[(size_t)w.z * D4_ + i], SP4[(size_t)(w.z >> 4) * D4_ + i]);
    float4 acc = f4sub(pe, ps);

    if (w.y != 0) {
        int row = (w.y > 0 ? w.y : -w.y) - 1;
        float sgn = (w.y > 0) ? 1.f : -1.f;
        float4 v = ldcs4(&x4[(size_t)row * D4_ + i]);
        acc = make_float4(fmaf(sgn, v.x, acc.x), fmaf(sgn, v.y, acc.y),
                          fmaf(sgn, v.z, acc.z), fmaf(sgn, v.w, acc.w));
    }
    if (w.w != 0) {
        int row = (w.w > 0 ? w.w : -w.w) - 1;
        float sgn = (w.w > 0) ? 1.f : -1.f;
        float4 v = ldcs4(&x4[(size_t)row * D4_ + i]);
        acc = make_float4(fmaf(sgn, v.x, acc.x), fmaf(sgn, v.y, acc.y),
                          fmaf(sgn, v.z, acc.z), fmaf(sgn, v.w, acc.w));
    }

    float4 o = make_float4(acc.x * invlen + EPS_, acc.y * invlen + EPS_,
                           acc.z * invlen + EPS_, acc.w * invlen + EPS_);
    stcs4(&out[(size_t)(2 * bt) * D4_ + i], o);
}

// ---------------------------------------------------------------------------
extern "C" void kernel_launch(void* const* d_in, const int* in_sizes, int n_in,
                              void* d_out, int out_size) {
    const float* x     = (const float*)d_in[0];
    const void*  graph = d_in[1];
    float*       out   = (float*)d_out;

    k_detect<<<1, 256>>>((const unsigned int*)graph);
    k_prep  <<<32, 256>>>(graph);
    k_fused <<<B_ * NCH, 256>>>((const float4*)x, (float4*)out);
    k_scan  <<<256, 256>>>();
    k_gather<<<B_ * STEPS, 256>>>((const float4*)x, (float4*)out);
}